// round 1
// baseline (speedup 1.0000x reference)
#include <cuda_runtime.h>

// RoPE: out[b,s,2k]   = c(s,k)*x[b,s,2k] - s(s,k)*x[b,s,2k+1]
//       out[b,s,2k+1] = s(s,k)*x[b,s,2k] + c(s,k)*x[b,s,2k+1]
// where c(s,k) = rot[s, 2k, 2k], s(s,k) = rot[s, 2k+1, 2k]
// (token_positions is overwritten with arange(S) in the reference forward,
//  so position == sequence index; the dense [S,128,128] matmul collapses
//  to per-pair 2x2 rotations.)
//
// B=32, S=4096, D=128. x: 64MB fp32 in, 64MB fp32 out -> HBM streaming bound.

#define BATCH 32
#define SEQ   4096
#define DK    128
#define PAIRS (DK / 2)          // 64
#define QUADS (DK / 4)          // 32 float4 per row

// 2MB scratch: (cos, sin) per (s, k). Stored as float2 so two consecutive
// pairs form one float4 for the main kernel.
__device__ float2 g_cs[SEQ * PAIRS];

// Gather the block-diagonal entries out of the 256MB rot tensor.
// One thread per (s, k).
__global__ void build_cs_table(const float* __restrict__ rot) {
    int idx = blockIdx.x * blockDim.x + threadIdx.x;
    if (idx >= SEQ * PAIRS) return;
    int s = idx >> 6;           // / PAIRS
    int k = idx & (PAIRS - 1);
    const float* base = rot + (size_t)s * (DK * DK);
    float c  = base[(2 * k) * DK + 2 * k];
    float sn = base[(2 * k + 1) * DK + 2 * k];
    g_cs[idx] = make_float2(c, sn);
}

// Main streaming kernel: one float4 of x (= 2 rotation pairs) per thread.
__global__ void rope_kernel(const float4* __restrict__ x,
                            float4* __restrict__ out) {
    int idx = blockIdx.x * blockDim.x + threadIdx.x;
    // idx layout: b * (SEQ*QUADS) + s * QUADS + q
    int q = idx & (QUADS - 1);
    int s = (idx >> 5) & (SEQ - 1);

    // table entries (s, 2q) and (s, 2q+1): two float2 = one float4
    float4 cs = reinterpret_cast<const float4*>(g_cs)[s * QUADS + q];
    float4 v = x[idx];

    float4 r;
    r.x = cs.x * v.x - cs.y * v.y;   // c0*xe - s0*xo
    r.y = cs.y * v.x + cs.x * v.y;   // s0*xe + c0*xo
    r.z = cs.z * v.z - cs.w * v.w;
    r.w = cs.w * v.z + cs.z * v.w;

    out[idx] = r;
}

extern "C" void kernel_launch(void* const* d_in, const int* in_sizes, int n_in,
                              void* d_out, int out_size) {
    const float* x   = (const float*)d_in[0];
    // d_in[1] = token_positions (int32) -- unused: reference overwrites it
    const float* rot = (const float*)d_in[2];

    {
        int total = SEQ * PAIRS;                  // 262144
        int threads = 256;
        build_cs_table<<<(total + threads - 1) / threads, threads>>>(rot);
    }
    {
        int total = BATCH * SEQ * QUADS;          // 4,194,304 float4
        int threads = 256;
        rope_kernel<<<total / threads, threads>>>(
            (const float4*)x, (float4*)d_out);
    }
}

// round 2
// speedup vs baseline: 1.2718x; 1.2718x over previous
#include <cuda_runtime.h>
#include <math.h>

// RoPE with positions == arange(S) (the reference forward overwrites
// token_positions). out[b,s,2k]   = c*x_e - s*x_o
//                   out[b,s,2k+1] = s*x_e + c*x_o
// with c = cos(s * w_k), s = sin(s * w_k), w_k = 10000^(-k/64).
//
// R1 showed the diagonal gather from the 256MB rot tensor costs ~20us
// (DRAM 32B-scatter, row-activate limited). We recompute the trig instead:
//  - w_k computed once in double (matches jax fp32 pow to ~1-2 ulp)
//  - angle = fl32(s * w_k)  (identical product rounding as reference)
//  - sincosf (<=2 ulp, same class as XLA cos/sin)
// Expected norm rel err ~1e-4 << 1e-3 threshold.

#define BATCH 32
#define SEQ   4096
#define DK    128
#define PAIRS (DK / 2)          // 64
#define QUADS (DK / 4)          // 32 float4 per row

__device__ float  g_w[PAIRS];           // w_k table (64 floats)
__device__ float2 g_cs[SEQ * PAIRS];    // 2MB (cos, sin) per (s, k)

// One tiny block: exact w_k in double precision, rounded to fp32.
__global__ void build_w_table() {
    int k = threadIdx.x;
    if (k < PAIRS) {
        double w = 1.0 / pow(10000.0, (double)k / 64.0);
        g_w[k] = (float)w;
    }
}

// 262144 threads: cos/sin table. Pure compute + 2MB streamed writes.
__global__ void build_cs_table() {
    int idx = blockIdx.x * blockDim.x + threadIdx.x;
    if (idx >= SEQ * PAIRS) return;
    int s = idx >> 6;           // / PAIRS
    int k = idx & (PAIRS - 1);
    float af = (float)s * g_w[k];   // same fp32 rounding as reference
    float sn, c;
    sincosf(af, &sn, &c);
    g_cs[idx] = make_float2(c, sn);
}

// Main streaming kernel: one float4 of x (= 2 rotation pairs) per thread.
__global__ void rope_kernel(const float4* __restrict__ x,
                            float4* __restrict__ out) {
    int idx = blockIdx.x * blockDim.x + threadIdx.x;
    // idx layout: b * (SEQ*QUADS) + s * QUADS + q
    int q = idx & (QUADS - 1);
    int s = (idx >> 5) & (SEQ - 1);

    // table entries (s, 2q) and (s, 2q+1): two float2 = one float4
    float4 cs = reinterpret_cast<const float4*>(g_cs)[s * QUADS + q];
    float4 v = x[idx];

    float4 r;
    r.x = cs.x * v.x - cs.y * v.y;   // c0*xe - s0*xo
    r.y = cs.y * v.x + cs.x * v.y;   // s0*xe + c0*xo
    r.z = cs.z * v.z - cs.w * v.w;
    r.w = cs.w * v.z + cs.z * v.w;

    out[idx] = r;
}

extern "C" void kernel_launch(void* const* d_in, const int* in_sizes, int n_in,
                              void* d_out, int out_size) {
    const float* x = (const float*)d_in[0];
    // d_in[1] = token_positions (unused: reference overwrites with arange)
    // d_in[2] = rot (unused: trig recomputed on device)

    build_w_table<<<1, 64>>>();
    {
        int total = SEQ * PAIRS;                  // 262144
        int threads = 256;
        build_cs_table<<<(total + threads - 1) / threads, threads>>>();
    }
    {
        int total = BATCH * SEQ * QUADS;          // 4,194,304 float4
        int threads = 256;
        rope_kernel<<<total / threads, threads>>>(
            (const float4*)x, (float4*)d_out);
    }
}

// round 3
// speedup vs baseline: 1.2890x; 1.0135x over previous
#include <cuda_runtime.h>
#include <math.h>

// Fully fused RoPE, positions == arange(S) (reference overwrites token_positions).
//   out[b,s,2k]   = cos(s*w_k)*x[b,s,2k]   - sin(s*w_k)*x[b,s,2k+1]
//   out[b,s,2k+1] = sin(s*w_k)*x[b,s,2k]   + cos(s*w_k)*x[b,s,2k+1]
//   w_k = 10000^(-k/64) = exp2(-k*log2(10000)/64)
//
// One thread owns one (s, q) float4 column (q = pair of rotation pairs) and
// loops over the 32 batches, so the 2x exp2f + 2x sincosf are computed once
// per 32 float4 load/stores. Pure HBM streaming: 64MB in + 64MB out.

#define BATCH 32
#define SEQ   4096
#define DK    128
#define QUADS (DK / 4)              // 32 float4 per row
#define COLS  (SEQ * QUADS)         // 131072 (s,q) columns

__global__ void rope_fused(const float4* __restrict__ x,
                           float4* __restrict__ out) {
    int idx = blockIdx.x * blockDim.x + threadIdx.x;   // 0..COLS-1
    int q = idx & (QUADS - 1);
    int s = idx >> 5;

    // -log2(10000)/64
    const float C = -0.2076205059304601f;
    float w0 = exp2f((float)(2 * q)     * C);
    float w1 = exp2f((float)(2 * q + 1) * C);

    float sf = (float)s;
    float s0, c0, s1, c1;
    sincosf(sf * w0, &s0, &c0);
    sincosf(sf * w1, &s1, &c1);

    size_t base = (size_t)idx;       // == s*QUADS + q
#pragma unroll
    for (int b = 0; b < BATCH; b++) {
        size_t off = base + (size_t)b * COLS;
        float4 v = __ldcs(x + off);
        float4 r;
        r.x = c0 * v.x - s0 * v.y;
        r.y = s0 * v.x + c0 * v.y;
        r.z = c1 * v.z - s1 * v.w;
        r.w = s1 * v.z + c1 * v.w;
        __stcs(out + off, r);
    }
}

extern "C" void kernel_launch(void* const* d_in, const int* in_sizes, int n_in,
                              void* d_out, int out_size) {
    const float* x = (const float*)d_in[0];
    // d_in[1] = token_positions (unused: reference overwrites with arange)
    // d_in[2] = rot (unused: trig recomputed on device)

    int threads = 256;
    rope_fused<<<COLS / threads, threads>>>((const float4*)x, (float4*)d_out);
}

// round 4
// speedup vs baseline: 1.7246x; 1.3380x over previous
#include <cuda_runtime.h>
#include <math.h>

// Fused RoPE, positions == arange(S) (reference overwrites token_positions).
//   out[b,s,2k]   = cos(s*w_k)*x[b,s,2k] - sin(s*w_k)*x[b,s,2k+1]
//   out[b,s,2k+1] = sin(s*w_k)*x[b,s,2k] + cos(s*w_k)*x[b,s,2k+1]
//   w_k = 10000^(-k/64) = exp2(-k*log2(10000)/64)
//
// R3 post-mortem: b=32 amortization shrank the grid to 512 CTAs -> occ 39.7%,
// DRAM 44.5%. MUFU cost is per-warp-instruction (trivial), so amortize over
// only 4 batches: grid = 4096 CTAs (full chip), trig ~1.3K cycles chip-wide.
// Pure HBM streaming: 64MB in + 64MB out, single launch.

#define BATCH   32
#define SEQ     4096
#define DK      128
#define QUADS   (DK / 4)            // 32 float4 per row
#define COLS    (SEQ * QUADS)       // 131072 (s,q) columns
#define BGROUP  4                   // batches per thread
#define NGROUPS (BATCH / BGROUP)    // 8

__global__ void rope_fused(const float4* __restrict__ x,
                           float4* __restrict__ out) {
    int idx = blockIdx.x * blockDim.x + threadIdx.x;   // 0 .. COLS*NGROUPS-1
    int col = idx & (COLS - 1);      // s*QUADS + q
    int g   = idx >> 17;             // batch group 0..7
    int q = col & (QUADS - 1);
    int s = col >> 5;

    // -log2(10000)/64
    const float C = -0.2076205059304601f;
    float w0 = exp2f((float)(2 * q)     * C);
    float w1 = exp2f((float)(2 * q + 1) * C);

    float sf = (float)s;
    float s0, c0, s1, c1;
    sincosf(sf * w0, &s0, &c0);
    sincosf(sf * w1, &s1, &c1);

    size_t base = (size_t)col + (size_t)g * (BGROUP * COLS);
#pragma unroll
    for (int i = 0; i < BGROUP; i++) {
        size_t off = base + (size_t)i * COLS;
        float4 v = __ldcs(x + off);
        float4 r;
        r.x = c0 * v.x - s0 * v.y;
        r.y = s0 * v.x + c0 * v.y;
        r.z = c1 * v.z - s1 * v.w;
        r.w = s1 * v.z + c1 * v.w;
        __stcs(out + off, r);
    }
}

extern "C" void kernel_launch(void* const* d_in, const int* in_sizes, int n_in,
                              void* d_out, int out_size) {
    const float* x = (const float*)d_in[0];
    // d_in[1] = token_positions (unused: reference overwrites with arange)
    // d_in[2] = rot (unused: trig recomputed on device)

    int threads = 256;
    int total = COLS * NGROUPS;                  // 1,048,576 threads
    rope_fused<<<total / threads, threads>>>((const float4*)x, (float4*)d_out);
}

// round 5
// speedup vs baseline: 1.8902x; 1.0960x over previous
#include <cuda_runtime.h>
#include <math.h>

// Fused RoPE, positions == arange(S) (reference overwrites token_positions).
//   out[b,s,2k]   = cos(s*w_k)*x[b,s,2k] - sin(s*w_k)*x[b,s,2k+1]
//   out[b,s,2k+1] = sin(s*w_k)*x[b,s,2k] + cos(s*w_k)*x[b,s,2k+1]
//   w_k = 10000^(-k/64) = exp2(-k*log2(10000)/64)
//
// R4: 19.5us kernel, occ 82%, DRAM 55%. This round: front-batch the 4
// LDG.128s BEFORE the MUFU trig so trig latency hides under DRAM latency
// and per-warp MLP_p1 rises to 4. Geometry unchanged (4096 CTAs x 256).

#define BATCH   32
#define SEQ     4096
#define DK      128
#define QUADS   (DK / 4)            // 32 float4 per row
#define COLS    (SEQ * QUADS)       // 131072 (s,q) columns
#define BGROUP  4                   // batches per thread
#define NGROUPS (BATCH / BGROUP)    // 8

__global__ void __launch_bounds__(256) rope_fused(
        const float4* __restrict__ x, float4* __restrict__ out) {
    int idx = blockIdx.x * blockDim.x + threadIdx.x;   // 0 .. COLS*NGROUPS-1
    int col = idx & (COLS - 1);      // s*QUADS + q
    int g   = idx >> 17;             // batch group 0..7
    int q = col & (QUADS - 1);
    int s = col >> 5;

    size_t base = (size_t)col + (size_t)g * (BGROUP * COLS);

    // Issue all 4 loads first: MLP=4, trig hides under DRAM latency.
    float4 v0 = x[base];
    float4 v1 = x[base + COLS];
    float4 v2 = x[base + 2 * COLS];
    float4 v3 = x[base + 3 * COLS];

    // -log2(10000)/64
    const float C = -0.2076205059304601f;
    float w0 = exp2f((float)(2 * q)     * C);
    float w1 = exp2f((float)(2 * q + 1) * C);

    float sf = (float)s;
    float s0, c0, s1, c1;
    sincosf(sf * w0, &s0, &c0);
    sincosf(sf * w1, &s1, &c1);

    float4 r;
    r.x = c0 * v0.x - s0 * v0.y;
    r.y = s0 * v0.x + c0 * v0.y;
    r.z = c1 * v0.z - s1 * v0.w;
    r.w = s1 * v0.z + c1 * v0.w;
    __stcs(out + base, r);

    r.x = c0 * v1.x - s0 * v1.y;
    r.y = s0 * v1.x + c0 * v1.y;
    r.z = c1 * v1.z - s1 * v1.w;
    r.w = s1 * v1.z + c1 * v1.w;
    __stcs(out + base + COLS, r);

    r.x = c0 * v2.x - s0 * v2.y;
    r.y = s0 * v2.x + c0 * v2.y;
    r.z = c1 * v2.z - s1 * v2.w;
    r.w = s1 * v2.z + c1 * v2.w;
    __stcs(out + base + 2 * COLS, r);

    r.x = c0 * v3.x - s0 * v3.y;
    r.y = s0 * v3.x + c0 * v3.y;
    r.z = c1 * v3.z - s1 * v3.w;
    r.w = s1 * v3.z + c1 * v3.w;
    __stcs(out + base + 3 * COLS, r);
}

extern "C" void kernel_launch(void* const* d_in, const int* in_sizes, int n_in,
                              void* d_out, int out_size) {
    const float* x = (const float*)d_in[0];
    // d_in[1] = token_positions (unused: reference overwrites with arange)
    // d_in[2] = rot (unused: trig recomputed on device)

    int threads = 256;
    int total = COLS * NGROUPS;                  // 1,048,576 threads
    rope_fused<<<total / threads, threads>>>((const float4*)x, (float4*)d_out);
}